// round 4
// baseline (speedup 1.0000x reference)
#include <cuda_runtime.h>

// B3-spline à-trous undecimated wavelet transform, J=3, fused single kernel.
// Input  x: (B, 1024, 1024) fp32.  Output: (B, 4, 1024, 1024) = [w1, w2, w3, c3].
//
// Tile = 64x64 output pixels per CTA, cascaded halo 14 (2+4+8), all
// intermediates in shared memory (3 ping-pong buffers, 92x93 fp32).
// Symmetric taps => conv(reflect(x)) == reflect(conv(x)), so one reflect-padded
// load of c0 reproduces the reference's per-level reflect padding exactly.
//
// Each separable 1-D pass: dst[c][r] = sum_k w_k src[r+k*d][c] (transposed
// store), 8-way register coarsening along r. Stride 93 (odd) keeps both the
// lane-contiguous reads and the transposed column writes bank-conflict-free.
//
// R3: input tile is loaded TRANSPOSED into smem (A[x][y]). The two transposing
// passes per level then leave every c-pass with x across lanes => the fused
// w_j / c_J global stores are fully coalesced 128B row segments. (R2's stores
// had lanes across rows: 32 cache lines per STG.128 -> L1 wavefront storm.)

#define IMG_H 1024
#define IMG_W 1024
#define TILE 64
#define STRIDE 93
#define BUF_FLOATS (92 * STRIDE)
#define SMEM_BYTES (3 * BUF_FLOATS * 4)
#define NW 16                    // warps per CTA

#define W0 0.0625f
#define W1 0.25f
#define W2 0.375f

__device__ __forceinline__ int refl(int i) {
    if (i < 0) return -i;
    if (i >= IMG_H) return 2 * IMG_H - 2 - i;
    return i;
}

// Plain pass: conv along the row dim of src, stored transposed.
template <int D, int RR, int RC>
__device__ __forceinline__ void tpass(const float* __restrict__ src,
                                      float* __restrict__ dst,
                                      int warp, int lane) {
    constexpr int GC = (RC + 31) / 32;
    constexpr int GR = RR / 8;
    constexpr int L = 8 + 4 * D;
    for (int g = warp; g < GC * GR; g += NW) {
        int c  = (g % GC) * 32 + lane;
        int r0 = (g / GC) * 8;
        if (c >= RC) continue;
        float v[L];
#pragma unroll
        for (int i = 0; i < L; i++) v[i] = src[(r0 + i) * STRIDE + c];
#pragma unroll
        for (int i = 0; i < 8; i++) {
            dst[c * STRIDE + r0 + i] =
                W0 * (v[i] + v[i + 4 * D]) + W1 * (v[i + D] + v[i + 3 * D]) +
                W2 * v[i + 2 * D];
        }
    }
}

// c-pass: completes level j (conv along src's row dim = y), optionally stores
// c_j to smem (transposed, back to [x][y]), and writes w_j = c_{j-1} - c_j
// (and c_J if LAST) to global memory. Here r indexes y, lane c indexes x, so
// the global stores are coalesced along x.
template <int D, int RR, int RC, int HALO, int PO, bool STORE, bool LAST>
__device__ __forceinline__ void cpass(const float* __restrict__ src,
                                      float* __restrict__ dst,
                                      const float* __restrict__ prev,
                                      float* __restrict__ gw,
                                      float* __restrict__ gc,
                                      int warp, int lane) {
    constexpr int GC = (RC + 31) / 32;
    constexpr int GR = RR / 8;
    constexpr int L = 8 + 4 * D;
    for (int g = warp; g < GC * GR; g += NW) {
        int c  = (g % GC) * 32 + lane;
        int r0 = (g / GC) * 8;
        if (c >= RC) continue;
        float v[L];
#pragma unroll
        for (int i = 0; i < L; i++) v[i] = src[(r0 + i) * STRIDE + c];
        float o[8];
#pragma unroll
        for (int i = 0; i < 8; i++) {
            o[i] = W0 * (v[i] + v[i + 4 * D]) + W1 * (v[i + D] + v[i + 3 * D]) +
                   W2 * v[i + 2 * D];
            if (STORE) dst[c * STRIDE + r0 + i] = o[i];
        }
        // Fused detail output: lane c = x (coalesced), register i = y.
        if (c >= HALO && c < HALO + TILE) {
            int xt = c - HALO;
            const float* pr = prev + (c + PO) * STRIDE + r0 + PO;
#pragma unroll
            for (int i = 0; i < 8; i++) {
                int yt = r0 + i - HALO;
                if (yt >= 0 && yt < TILE) {
                    gw[(size_t)yt * IMG_W + xt] = pr[i] - o[i];
                    if (LAST) gc[(size_t)yt * IMG_W + xt] = o[i];
                }
            }
        }
    }
}

__global__ __launch_bounds__(32 * NW, 2)
void uwt_kernel(const float* __restrict__ x, float* __restrict__ out) {
    extern __shared__ float sm[];
    float* A  = sm;
    float* Bb = sm + BUF_FLOATS;
    float* Cc = sm + 2 * BUF_FLOATS;

    const int tid  = threadIdx.x;
    const int lane = tid & 31;
    const int warp = tid >> 5;
    const int tx0  = blockIdx.x * TILE;
    const int ty0  = blockIdx.y * TILE;
    const int b    = blockIdx.z;

    const float* xb = x + (size_t)b * IMG_H * IMG_W;

    // Load c0 region 92x92 (origin ty0-14, tx0-14, reflect) TRANSPOSED into
    // A[x][y]. Gmem read coalesced along x; smem store conflict-free (odd stride).
    for (int yl = warp; yl < 92; yl += NW) {
        const float* row = xb + (size_t)refl(ty0 - 14 + yl) * IMG_W;
#pragma unroll
        for (int cg = 0; cg < 3; cg++) {
            int xl = cg * 32 + lane;
            if (xl < 92) A[xl * STRIDE + yl] = row[refl(tx0 - 14 + xl)];
        }
    }
    __syncthreads();

    float* base = out + (size_t)b * 4 * IMG_H * IMG_W;
    float* w1p = base + 0 * (size_t)IMG_H * IMG_W + (size_t)ty0 * IMG_W + tx0;
    float* w2p = base + 1 * (size_t)IMG_H * IMG_W + (size_t)ty0 * IMG_W + tx0;
    float* w3p = base + 2 * (size_t)IMG_H * IMG_W + (size_t)ty0 * IMG_W + tx0;
    float* c3p = base + 3 * (size_t)IMG_H * IMG_W + (size_t)ty0 * IMG_W + tx0;

    // Level 1 (d=1): convX -> B[y][x]; convY -> C[x][y] = c1; emit w1.
    tpass<1, 88, 92>(A, Bb, warp, lane);
    __syncthreads();
    cpass<1, 88, 88, 12, 2, true, false>(Bb, Cc, A, w1p, nullptr, warp, lane);
    __syncthreads();

    // Level 2 (d=2): convX -> A[y][x]; convY -> B[x][y] = c2; emit w2.
    tpass<2, 80, 88>(Cc, A, warp, lane);
    __syncthreads();
    cpass<2, 80, 80, 8, 4, true, false>(A, Bb, Cc, w2p, nullptr, warp, lane);
    __syncthreads();

    // Level 3 (d=4): convX -> C[y][x]; convY (not stored); emit w3 and c3.
    tpass<4, 64, 80>(Bb, Cc, warp, lane);
    __syncthreads();
    cpass<4, 64, 64, 0, 8, false, true>(Cc, nullptr, Bb, w3p, c3p, warp, lane);
}

extern "C" void kernel_launch(void* const* d_in, const int* in_sizes, int n_in,
                              void* d_out, int out_size) {
    const float* x = (const float*)d_in[0];
    float* out = (float*)d_out;
    int batch = in_sizes[0] / (IMG_H * IMG_W);

    cudaFuncSetAttribute(uwt_kernel, cudaFuncAttributeMaxDynamicSharedMemorySize,
                         SMEM_BYTES);

    dim3 grid(IMG_W / TILE, IMG_H / TILE, batch);
    dim3 block(32 * NW);
    uwt_kernel<<<grid, block, SMEM_BYTES>>>(x, out);
}

// round 6
// speedup vs baseline: 1.5555x; 1.5555x over previous
#include <cuda_runtime.h>

// B3-spline à-trous undecimated wavelet transform, J=3, fused single kernel.
// Input  x: (B, 1024, 1024) fp32.  Output: (B, 4, 1024, 1024) = [w1, w2, w3, c3].
//
// Tile = 64x64 output pixels per CTA, cascaded halo 14 (2+4+8), all
// intermediates in shared memory (3 ping-pong buffers, 92x93 fp32).
// Symmetric taps => conv(reflect(x)) == reflect(conv(x)), so one reflect-padded
// load of c0 reproduces the reference's per-level reflect padding exactly.
//
// R4 structure: every separable 1-D pass is a pure smem->smem tpass
// (transposed store, 8-way register coarsening, odd stride 93 => conflict-free
// in both directions). Two tpasses per level return the c_j buffer to natural
// [y][x] orientation, so a tiny separate writeout loop emits w_j = c_{j-1}-c_j
// (and c_3) with fully coalesced 128B/warp stores and consecutive-address smem
// reads. This avoids both R2's scattered stores and R3's predicated scalar
// store storm inside the conv pass.

#define IMG_H 1024
#define IMG_W 1024
#define TILE 64
#define STRIDE 93
#define BUF_FLOATS (92 * STRIDE)
#define SMEM_BYTES (3 * BUF_FLOATS * 4)
#define NW 16                    // warps per CTA (512 threads)

#define W0 0.0625f
#define W1 0.25f
#define W2 0.375f

__device__ __forceinline__ int refl(int i) {
    if (i < 0) return -i;
    if (i >= IMG_H) return 2 * IMG_H - 2 - i;
    return i;
}

// Pure conv pass along the row dim of src, stored transposed.
// RR: output rows (multiple of 8), RC: cols carried through. D: dilation.
template <int D, int RR, int RC>
__device__ __forceinline__ void tpass(const float* __restrict__ src,
                                      float* __restrict__ dst,
                                      int warp, int lane) {
    constexpr int GC = (RC + 31) / 32;
    constexpr int GR = RR / 8;
    constexpr int L = 8 + 4 * D;
    for (int g = warp; g < GC * GR; g += NW) {
        int c  = (g % GC) * 32 + lane;
        int r0 = (g / GC) * 8;
        if (c >= RC) continue;
        float v[L];
#pragma unroll
        for (int i = 0; i < L; i++) v[i] = src[(r0 + i) * STRIDE + c];
#pragma unroll
        for (int i = 0; i < 8; i++) {
            dst[c * STRIDE + r0 + i] =
                W0 * (v[i] + v[i + 4 * D]) + W1 * (v[i + D] + v[i + 3 * D]) +
                W2 * v[i + 2 * D];
        }
    }
}

// Coalesced writeout: w = prev - cur (both [y][x] in smem), optional c_J.
// 512 threads, 8 rows apart; 2 LDS + 1-2 STG per output, strength-reduced.
template <int HP, int HC, bool LAST>
__device__ __forceinline__ void writeout(const float* __restrict__ prev,
                                         const float* __restrict__ cur,
                                         float* __restrict__ gw,
                                         float* __restrict__ gc, int tid) {
    int yt = tid >> 6;           // 0..7
    int xt = tid & 63;
    const float* pp = prev + (HP + yt) * STRIDE + HP + xt;
    const float* cp = cur + (HC + yt) * STRIDE + HC + xt;
    float* gwp = gw + (size_t)yt * IMG_W + xt;
    float* gcp = gc + (size_t)yt * IMG_W + xt;
#pragma unroll
    for (int i = 0; i < 8; i++) {
        float cv = cp[i * 8 * STRIDE];
        gwp[(size_t)i * 8 * IMG_W] = pp[i * 8 * STRIDE] - cv;
        if (LAST) gcp[(size_t)i * 8 * IMG_W] = cv;
    }
}

__global__ __launch_bounds__(32 * NW, 2)
void uwt_kernel(const float* __restrict__ x, float* __restrict__ out) {
    extern __shared__ float sm[];
    float* A  = sm;                      // c0[y][x] -> t2 -> c3[y][x]
    float* Bb = sm + BUF_FLOATS;         // t1 -> c2[y][x]
    float* Cc = sm + 2 * BUF_FLOATS;     // c1[y][x] -> t3

    const int tid  = threadIdx.x;
    const int lane = tid & 31;
    const int warp = tid >> 5;
    const int tx0  = blockIdx.x * TILE;
    const int ty0  = blockIdx.y * TILE;
    const int b    = blockIdx.z;

    const float* xb = x + (size_t)b * IMG_H * IMG_W;

    // Load c0 region: 92x92, origin (ty0-14, tx0-14), reflect-padded, [y][x].
    for (int r = warp; r < 92; r += NW) {
        const float* row = xb + (size_t)refl(ty0 - 14 + r) * IMG_W;
#pragma unroll
        for (int cg = 0; cg < 3; cg++) {
            int c = cg * 32 + lane;
            if (c < 92) A[r * STRIDE + c] = row[refl(tx0 - 14 + c)];
        }
    }
    __syncthreads();

    float* base = out + (size_t)b * 4 * IMG_H * IMG_W;
    float* w1p = base + 0 * (size_t)IMG_H * IMG_W + (size_t)ty0 * IMG_W + tx0;
    float* w2p = base + 1 * (size_t)IMG_H * IMG_W + (size_t)ty0 * IMG_W + tx0;
    float* w3p = base + 2 * (size_t)IMG_H * IMG_W + (size_t)ty0 * IMG_W + tx0;
    float* c3p = base + 3 * (size_t)IMG_H * IMG_W + (size_t)ty0 * IMG_W + tx0;

    // Level 1 (d=1): A(c0)[y][x] -> B[x][y] -> C(c1)[y][x]  (88x88, off +2)
    tpass<1, 88, 92>(A, Bb, warp, lane);
    __syncthreads();
    tpass<1, 88, 88>(Bb, Cc, warp, lane);
    __syncthreads();
    writeout<14, 12, false>(A, Cc, w1p, nullptr, tid);
    __syncthreads();

    // Level 2 (d=2): C(c1) -> A[x][y] -> B(c2)[y][x]  (80x80, off +4 vs c1)
    tpass<2, 80, 88>(Cc, A, warp, lane);
    __syncthreads();
    tpass<2, 80, 80>(A, Bb, warp, lane);
    __syncthreads();
    writeout<12, 8, false>(Cc, Bb, w2p, nullptr, tid);
    __syncthreads();

    // Level 3 (d=4): B(c2) -> C[x][y] -> A(c3)[y][x]  (64x64, off +8 vs c2)
    tpass<4, 64, 80>(Bb, Cc, warp, lane);
    __syncthreads();
    tpass<4, 64, 64>(Cc, A, warp, lane);
    __syncthreads();
    writeout<8, 0, true>(Bb, A, w3p, c3p, tid);
}

extern "C" void kernel_launch(void* const* d_in, const int* in_sizes, int n_in,
                              void* d_out, int out_size) {
    const float* x = (const float*)d_in[0];
    float* out = (float*)d_out;
    int batch = in_sizes[0] / (IMG_H * IMG_W);

    cudaFuncSetAttribute(uwt_kernel, cudaFuncAttributeMaxDynamicSharedMemorySize,
                         SMEM_BYTES);

    dim3 grid(IMG_W / TILE, IMG_H / TILE, batch);
    dim3 block(32 * NW);
    uwt_kernel<<<grid, block, SMEM_BYTES>>>(x, out);
}

// round 7
// speedup vs baseline: 1.6337x; 1.0503x over previous
#include <cuda_runtime.h>

// B3-spline à-trous undecimated wavelet transform, J=3, fused single kernel.
// Input  x: (B, 1024, 1024) fp32.  Output: (B, 4, 1024, 1024) = [w1, w2, w3, c3].
//
// Tile = 64x64 output pixels per CTA, cascaded halo 14 (2+4+8), all
// intermediates in shared memory (3 ping-pong buffers, 92x93 fp32).
// Symmetric taps => conv(reflect(x)) == reflect(conv(x)), so one reflect-padded
// load of c0 reproduces the reference's per-level reflect padding exactly.
//
// Structure (R4): pure smem->smem transposing conv passes (odd stride 93 =>
// conflict-free lane-contiguous reads AND transposed column writes), plus a
// dedicated coalesced writeout per level reading c_{j-1} and c_j (both [y][x])
// at consecutive smem addresses and storing 128B/warp row segments.
//
// R5: 768 threads/CTA (24 warps), still 2 CTAs/SM => 48 resident warps (71%
// occ, was 47%). Profile showed issue 50.6% / L1 56% / nothing saturated:
// latency-bound for lack of warps. regs 39*768*2 = 60K <= 64K regfile.

#define IMG_H 1024
#define IMG_W 1024
#define TILE 64
#define STRIDE 93
#define BUF_FLOATS (92 * STRIDE)
#define SMEM_BYTES (3 * BUF_FLOATS * 4)
#define NW 24                    // warps per CTA (768 threads)

#define W0 0.0625f
#define W1 0.25f
#define W2 0.375f

__device__ __forceinline__ int refl(int i) {
    if (i < 0) return -i;
    if (i >= IMG_H) return 2 * IMG_H - 2 - i;
    return i;
}

// Pure conv pass along the row dim of src, stored transposed.
// RR: output rows (multiple of 8), RC: cols carried through. D: dilation.
template <int D, int RR, int RC>
__device__ __forceinline__ void tpass(const float* __restrict__ src,
                                      float* __restrict__ dst,
                                      int warp, int lane) {
    constexpr int GC = (RC + 31) / 32;
    constexpr int GR = RR / 8;
    constexpr int L = 8 + 4 * D;
    for (int g = warp; g < GC * GR; g += NW) {
        int c  = (g % GC) * 32 + lane;
        int r0 = (g / GC) * 8;
        if (c >= RC) continue;
        float v[L];
#pragma unroll
        for (int i = 0; i < L; i++) v[i] = src[(r0 + i) * STRIDE + c];
#pragma unroll
        for (int i = 0; i < 8; i++) {
            dst[c * STRIDE + r0 + i] =
                W0 * (v[i] + v[i + 4 * D]) + W1 * (v[i + D] + v[i + 3 * D]) +
                W2 * v[i + 2 * D];
        }
    }
}

// Coalesced writeout: w = prev - cur (both [y][x] in smem), optional c_J.
// 768 threads cover 12 rows x 64 cols; rows strided by 12 over the 64-row tile.
template <int HP, int HC, bool LAST>
__device__ __forceinline__ void writeout(const float* __restrict__ prev,
                                         const float* __restrict__ cur,
                                         float* __restrict__ gw,
                                         float* __restrict__ gc, int tid) {
    int yt = tid >> 6;           // 0..11
    int xt = tid & 63;
    const float* pp = prev + (HP + yt) * STRIDE + HP + xt;
    const float* cp = cur + (HC + yt) * STRIDE + HC + xt;
    float* gwp = gw + (size_t)yt * IMG_W + xt;
    float* gcp = gc + (size_t)yt * IMG_W + xt;
#pragma unroll
    for (int i = 0; i < 6; i++) {
        int y = yt + i * 12;
        if (y < TILE) {
            float cv = cp[i * 12 * STRIDE];
            gwp[(size_t)i * 12 * IMG_W] = pp[i * 12 * STRIDE] - cv;
            if (LAST) gcp[(size_t)i * 12 * IMG_W] = cv;
        }
    }
}

__global__ __launch_bounds__(32 * NW, 2)
void uwt_kernel(const float* __restrict__ x, float* __restrict__ out) {
    extern __shared__ float sm[];
    float* A  = sm;                      // c0[y][x] -> t2 -> c3[y][x]
    float* Bb = sm + BUF_FLOATS;         // t1 -> c2[y][x]
    float* Cc = sm + 2 * BUF_FLOATS;     // c1[y][x] -> t3

    const int tid  = threadIdx.x;
    const int lane = tid & 31;
    const int warp = tid >> 5;
    const int tx0  = blockIdx.x * TILE;
    const int ty0  = blockIdx.y * TILE;
    const int b    = blockIdx.z;

    const float* xb = x + (size_t)b * IMG_H * IMG_W;

    // Load c0 region: 92x92, origin (ty0-14, tx0-14), reflect-padded, [y][x].
    for (int r = warp; r < 92; r += NW) {
        const float* row = xb + (size_t)refl(ty0 - 14 + r) * IMG_W;
#pragma unroll
        for (int cg = 0; cg < 3; cg++) {
            int c = cg * 32 + lane;
            if (c < 92) A[r * STRIDE + c] = row[refl(tx0 - 14 + c)];
        }
    }
    __syncthreads();

    float* base = out + (size_t)b * 4 * IMG_H * IMG_W;
    float* w1p = base + 0 * (size_t)IMG_H * IMG_W + (size_t)ty0 * IMG_W + tx0;
    float* w2p = base + 1 * (size_t)IMG_H * IMG_W + (size_t)ty0 * IMG_W + tx0;
    float* w3p = base + 2 * (size_t)IMG_H * IMG_W + (size_t)ty0 * IMG_W + tx0;
    float* c3p = base + 3 * (size_t)IMG_H * IMG_W + (size_t)ty0 * IMG_W + tx0;

    // Level 1 (d=1): A(c0)[y][x] -> B[x][y] -> C(c1)[y][x]  (88x88, off +2)
    tpass<1, 88, 92>(A, Bb, warp, lane);
    __syncthreads();
    tpass<1, 88, 88>(Bb, Cc, warp, lane);
    __syncthreads();
    writeout<14, 12, false>(A, Cc, w1p, nullptr, tid);
    __syncthreads();

    // Level 2 (d=2): C(c1) -> A[x][y] -> B(c2)[y][x]  (80x80, off +4 vs c1)
    tpass<2, 80, 88>(Cc, A, warp, lane);
    __syncthreads();
    tpass<2, 80, 80>(A, Bb, warp, lane);
    __syncthreads();
    writeout<12, 8, false>(Cc, Bb, w2p, nullptr, tid);
    __syncthreads();

    // Level 3 (d=4): B(c2) -> C[x][y] -> A(c3)[y][x]  (64x64, off +8 vs c2)
    tpass<4, 64, 80>(Bb, Cc, warp, lane);
    __syncthreads();
    tpass<4, 64, 64>(Cc, A, warp, lane);
    __syncthreads();
    writeout<8, 0, true>(Bb, A, w3p, c3p, tid);
}

extern "C" void kernel_launch(void* const* d_in, const int* in_sizes, int n_in,
                              void* d_out, int out_size) {
    const float* x = (const float*)d_in[0];
    float* out = (float*)d_out;
    int batch = in_sizes[0] / (IMG_H * IMG_W);

    cudaFuncSetAttribute(uwt_kernel, cudaFuncAttributeMaxDynamicSharedMemorySize,
                         SMEM_BYTES);

    dim3 grid(IMG_W / TILE, IMG_H / TILE, batch);
    dim3 block(32 * NW);
    uwt_kernel<<<grid, block, SMEM_BYTES>>>(x, out);
}

// round 9
// speedup vs baseline: 1.7251x; 1.0559x over previous
#include <cuda_runtime.h>

// B3-spline à-trous undecimated wavelet transform, J=3, fused single kernel.
// Input  x: (B, 1024, 1024) fp32.  Output: (B, 4, 1024, 1024) = [w1, w2, w3, c3].
//
// Tile = 64x64 output pixels per CTA, cascaded halo 14 (2+4+8), all
// intermediates in shared memory (3 ping-pong buffers, 92 x STRIDE fp32).
// Symmetric taps => conv(reflect(x)) == reflect(conv(x)): one reflect-padded
// c0 load reproduces the reference's per-level reflect padding exactly.
//
// R7: (a) STRIDE=100 with STS.128 transposed stores: 100 = 4 (mod 32) makes
// the 8-lane 128-bit store phases hit disjoint 4-bank groups (conflict-free)
// and scalar lane-contiguous loads stay conflict-free; 8 scalar STS -> 2
// STS.128 per group. (b) writeout1/2 fused into the next level's first tpass
// phase (buffer-lifetime safe: t-buffers are dead exactly then): 9 phases -> 7,
// better per-phase work balance.
//
// Buffers: A: c0 -> c2; B: t1 -> t2 -> t3; C: c1 -> c3.

#define IMG_H 1024
#define IMG_W 1024
#define TILE 64
#define STRIDE 100
#define BUF_FLOATS (92 * STRIDE)
#define SMEM_BYTES (3 * BUF_FLOATS * 4)
#define NW 24                    // warps per CTA (768 threads)

#define W0 0.0625f
#define W1 0.25f
#define W2 0.375f

__device__ __forceinline__ int refl(int i) {
    if (i < 0) return -i;
    if (i >= IMG_H) return 2 * IMG_H - 2 - i;
    return i;
}

// Conv pass along the row dim of src, stored transposed with STS.128.
// RR: output rows (multiple of 8), RC: cols carried through. D: dilation.
template <int D, int RR, int RC>
__device__ __forceinline__ void tpass(const float* __restrict__ src,
                                      float* __restrict__ dst,
                                      int warp, int lane) {
    constexpr int GC = (RC + 31) / 32;
    constexpr int GR = RR / 8;
    constexpr int L = 8 + 4 * D;
    for (int g = warp; g < GC * GR; g += NW) {
        int c  = (g % GC) * 32 + lane;
        int r0 = (g / GC) * 8;
        if (c >= RC) continue;
        float v[L];
#pragma unroll
        for (int i = 0; i < L; i++) v[i] = src[(r0 + i) * STRIDE + c];
        float o[8];
#pragma unroll
        for (int i = 0; i < 8; i++) {
            o[i] = W0 * (v[i] + v[i + 4 * D]) + W1 * (v[i + D] + v[i + 3 * D]) +
                   W2 * v[i + 2 * D];
        }
        float4* dp = (float4*)(dst + c * STRIDE + r0);   // 16B-aligned: 100c+r0 % 4 == 0
        dp[0] = make_float4(o[0], o[1], o[2], o[3]);
        dp[1] = make_float4(o[4], o[5], o[6], o[7]);
    }
}

// Coalesced writeout: w = prev - cur (both [y][x] in smem), optional c_J.
// 768 threads cover 12 rows x 64 cols; rows strided by 12 over 64.
template <int HP, int HC, bool LAST>
__device__ __forceinline__ void writeout(const float* __restrict__ prev,
                                         const float* __restrict__ cur,
                                         float* __restrict__ gw,
                                         float* __restrict__ gc, int tid) {
    int yt = tid >> 6;           // 0..11
    int xt = tid & 63;
    const float* pp = prev + (HP + yt) * STRIDE + HP + xt;
    const float* cp = cur + (HC + yt) * STRIDE + HC + xt;
    float* gwp = gw + (size_t)yt * IMG_W + xt;
    float* gcp = gc + (size_t)yt * IMG_W + xt;
#pragma unroll
    for (int i = 0; i < 6; i++) {
        int y = yt + i * 12;
        if (y < TILE) {
            float cv = cp[i * 12 * STRIDE];
            gwp[(size_t)i * 12 * IMG_W] = pp[i * 12 * STRIDE] - cv;
            if (LAST) gcp[(size_t)i * 12 * IMG_W] = cv;
        }
    }
}

__global__ __launch_bounds__(32 * NW, 2)
void uwt_kernel(const float* __restrict__ x, float* __restrict__ out) {
    extern __shared__ float sm[];
    float* A  = sm;                      // c0[y][x] -> c2[y][x]
    float* Bb = sm + BUF_FLOATS;         // t1 -> t2 -> t3
    float* Cc = sm + 2 * BUF_FLOATS;     // c1[y][x] -> c3[y][x]

    const int tid  = threadIdx.x;
    const int lane = tid & 31;
    const int warp = tid >> 5;
    const int tx0  = blockIdx.x * TILE;
    const int ty0  = blockIdx.y * TILE;
    const int b    = blockIdx.z;

    const float* xb = x + (size_t)b * IMG_H * IMG_W;

    // Load c0 region: 92x92, origin (ty0-14, tx0-14), reflect-padded, [y][x].
    for (int r = warp; r < 92; r += NW) {
        const float* row = xb + (size_t)refl(ty0 - 14 + r) * IMG_W;
#pragma unroll
        for (int cg = 0; cg < 3; cg++) {
            int c = cg * 32 + lane;
            if (c < 92) A[r * STRIDE + c] = row[refl(tx0 - 14 + c)];
        }
    }
    __syncthreads();

    float* base = out + (size_t)b * 4 * IMG_H * IMG_W;
    float* w1p = base + 0 * (size_t)IMG_H * IMG_W + (size_t)ty0 * IMG_W + tx0;
    float* w2p = base + 1 * (size_t)IMG_H * IMG_W + (size_t)ty0 * IMG_W + tx0;
    float* w3p = base + 2 * (size_t)IMG_H * IMG_W + (size_t)ty0 * IMG_W + tx0;
    float* c3p = base + 3 * (size_t)IMG_H * IMG_W + (size_t)ty0 * IMG_W + tx0;

    // P1: t1 = convY(c0): A -> B[x][y]   (88 rows out, 92 cols)
    tpass<1, 88, 92>(A, Bb, warp, lane);
    __syncthreads();
    // P2: c1 = convX(t1): B -> C[y][x]   (88x88, offset +2 vs c0 region)
    tpass<1, 88, 88>(Bb, Cc, warp, lane);
    __syncthreads();
    // P3: t2 = convY(c1): C -> B[x][y]; fused w1 = c0 - c1 (A,C alive, B dead)
    tpass<2, 80, 88>(Cc, Bb, warp, lane);
    writeout<14, 12, false>(A, Cc, w1p, nullptr, tid);
    __syncthreads();
    // P4: c2 = convX(t2): B -> A[y][x]   (80x80, offset +4 vs c1; c0 now dead)
    tpass<2, 80, 80>(Bb, A, warp, lane);
    __syncthreads();
    // P5: t3 = convY(c2): A -> B[x][y]; fused w2 = c1 - c2 (C=c1, A=c2 alive)
    tpass<4, 64, 80>(A, Bb, warp, lane);
    writeout<12, 8, false>(Cc, A, w2p, nullptr, tid);
    __syncthreads();
    // P6: c3 = convX(t3): B -> C[y][x]   (64x64, offset +8 vs c2; c1 now dead)
    tpass<4, 64, 64>(Bb, Cc, warp, lane);
    __syncthreads();
    // P7: w3 = c2 - c3, and c3.
    writeout<8, 0, true>(A, Cc, w3p, c3p, tid);
}

extern "C" void kernel_launch(void* const* d_in, const int* in_sizes, int n_in,
                              void* d_out, int out_size) {
    const float* x = (const float*)d_in[0];
    float* out = (float*)d_out;
    int batch = in_sizes[0] / (IMG_H * IMG_W);

    cudaFuncSetAttribute(uwt_kernel, cudaFuncAttributeMaxDynamicSharedMemorySize,
                         SMEM_BYTES);

    dim3 grid(IMG_W / TILE, IMG_H / TILE, batch);
    dim3 block(32 * NW);
    uwt_kernel<<<grid, block, SMEM_BYTES>>>(x, out);
}